// round 1
// baseline (speedup 1.0000x reference)
#include <cuda_runtime.h>
#include <math.h>

#define N        2048
#define THREADS  256
#define EPN      8   // elements per thread

__device__ __forceinline__ float logaddexpf_(float a, float b) {
    float mx = fmaxf(a, b);
    float mn = fminf(a, b);
    return mx + log1pf(expf(mn - mx));
}

__global__ void __launch_bounds__(THREADS, 4)
soft_spearman_kernel(const float* __restrict__ x1,
                     const float* __restrict__ x2,
                     float* __restrict__ out)
{
    // 16KB: sort buffer, later aliased as two float[2048] PAV stack arrays /
    // prefix-min & suffix-max arrays
    __shared__ unsigned long long keybuf[N];
    __shared__ float          v0s[N];       // 8KB: s - log(n-i)
    __shared__ unsigned short perm[N];      // 4KB: low 11 bits = orig idx, bit15 = boundary flag
    __shared__ unsigned short ststart[N];   // 4KB: PAV stack block-start indices
    __shared__ float          rank1[N];     // 8KB: row-1 ranks in original order
    __shared__ float          scrA[THREADS];
    __shared__ float          scrB[THREADS];
    __shared__ float          redC[8];
    __shared__ float          bcast[8];

    const int row = blockIdx.x;
    const int tid = threadIdx.x;

    float* stack_ly = (float*)keybuf;          // [0..N)
    float* stack_lw = ((float*)keybuf) + N;    // [N..2N)
    float* prefm = stack_ly;                   // alias (scans happen before stacks)
    float* sufm  = stack_lw;

    for (int r = 0; r < 2; ++r) {
        const float* x = (r == 0 ? x1 : x2) + (size_t)row * N;

        // ---- build sort keys: ascending key == descending theta, stable ties ----
        #pragma unroll
        for (int e = 0; e < EPN; ++e) {
            int i = tid + e * THREADS;
            float f = x[i] / 0.1f;                       // theta = x / EPS
            unsigned u = __float_as_uint(f);
            u = (u & 0x80000000u) ? ~u : (u | 0x80000000u);  // order-preserving map
            keybuf[i] = (((unsigned long long)(~u)) << 32) | (unsigned)i;
        }
        __syncthreads();

        // ---- in-place bitonic sort (ascending) ----
        for (int k = 2; k <= N; k <<= 1) {
            for (int j = k >> 1; j > 0; j >>= 1) {
                #pragma unroll 4
                for (int t = tid; t < N / 2; t += THREADS) {
                    int i   = ((t & ~(j - 1)) << 1) | (t & (j - 1));
                    int ixj = i | j;
                    unsigned long long A  = keybuf[i];
                    unsigned long long Bv = keybuf[ixj];
                    bool up = ((i & k) == 0);
                    if ((A > Bv) == up) { keybuf[i] = Bv; keybuf[ixj] = A; }
                }
                __syncthreads();
            }
        }

        // ---- extract v0 = s - log(n-i) and permutation ----
        #pragma unroll
        for (int e = 0; e < EPN; ++e) {
            int i = tid * EPN + e;
            unsigned long long K = keybuf[i];
            unsigned idx  = (unsigned)K;
            unsigned u    = ~((unsigned)(K >> 32));
            unsigned bits = (u & 0x80000000u) ? (u ^ 0x80000000u) : ~u;
            float s = __uint_as_float(bits);
            v0s[i]  = s - logf((float)(N - i));
            perm[i] = (unsigned short)idx;
        }
        __syncthreads();

        // ---- prefix-min / suffix-max of v0 (chunk-local + block scan) ----
        {
            int base = tid * EPN;
            float cmin = v0s[base], cmax = cmin;
            #pragma unroll
            for (int e = 1; e < EPN; ++e) {
                float f = v0s[base + e];
                cmin = fminf(cmin, f);
                cmax = fmaxf(cmax, f);
            }
            scrA[tid] = cmin;
            scrB[tid] = cmax;
            __syncthreads();
            for (int d = 1; d < THREADS; d <<= 1) {
                float a_cur = scrA[tid];
                float b_cur = scrB[tid];
                float a_prv = (tid >= d) ? scrA[tid - d] : 3.0e38f;
                float b_nxt = (tid + d < THREADS) ? scrB[tid + d] : -3.0e38f;
                __syncthreads();
                scrA[tid] = fminf(a_cur, a_prv);
                scrB[tid] = fmaxf(b_cur, b_nxt);
                __syncthreads();
            }
            float run = (tid > 0) ? scrA[tid - 1] : 3.0e38f;
            #pragma unroll
            for (int e = 0; e < EPN; ++e) {
                run = fminf(run, v0s[base + e]);
                prefm[base + e] = run;
            }
            float runx = (tid < THREADS - 1) ? scrB[tid + 1] : -3.0e38f;
            #pragma unroll
            for (int e = EPN - 1; e >= 0; --e) {
                runx = fmaxf(runx, v0s[base + e]);
                sufm[base + e] = runx;
            }
            __syncthreads();

            // guaranteed-boundary flags: prefmin[i] > sufmax[i+1]
            #pragma unroll
            for (int e = 0; e < EPN; ++e) {
                int i = base + e;
                if (i < N - 1 && prefm[i] > sufm[i + 1])
                    perm[i] |= 0x8000;
            }
            __syncthreads();
        }

        // ---- segmented PAV + fused emit (stacks alias keybuf region) ----
        float asum = 0.0f, asq = 0.0f, adot = 0.0f;
        float m1v = (r == 1) ? bcast[2] : 0.0f;

        for (int i0 = tid; i0 < N; i0 += THREADS) {
            bool isStart = (i0 == 0) || (perm[i0 - 1] & 0x8000);
            if (!isStart) continue;

            float cv     = v0s[i0];
            float clw    = logf((float)(N - i0));
            float cly    = cv + clw;
            int   cstart = i0;
            int   top    = -1;
            int   i      = i0;

            while (i + 1 < N && !(perm[i] & 0x8000)) {
                ++i;
                float v   = v0s[i];
                float lwi = logf((float)(N - i));
                if (cv > v) {
                    // strictly decreasing: push current block, start new
                    ++top;
                    stack_ly[i0 + top] = cly;
                    stack_lw[i0 + top] = clw;
                    ststart [i0 + top] = (unsigned short)cstart;
                    cly = v + lwi; clw = lwi; cv = v; cstart = i;
                } else {
                    // merge element i into current block, cascade left
                    cly = logaddexpf_(cly, v + lwi);
                    clw = logaddexpf_(clw, lwi);
                    cv  = cly - clw;
                    while (top >= 0) {
                        float ply = stack_ly[i0 + top];
                        float plw = stack_lw[i0 + top];
                        if (ply - plw > cv) break;
                        cly = logaddexpf_(ply, cly);
                        clw = logaddexpf_(plw, clw);
                        cv  = cly - clw;
                        cstart = ststart[i0 + top];
                        --top;
                    }
                }
            }

            // emit blocks back-to-front; fuse rank computation + scatter + moments
            int eend = i;
            for (;;) {
                for (int j = cstart; j <= eend; ++j) {
                    float rk = (float)(N - j) * expf(v0s[j] - cv);
                    int   p  = perm[j] & 0x7FF;
                    if (r == 0) {
                        rank1[p] = rk;
                        asum += rk; asq += rk * rk;
                    } else {
                        asum += rk; asq += rk * rk;
                        adot += rk * (rank1[p] - m1v);
                    }
                }
                if (top < 0) break;
                eend   = cstart - 1;
                cly    = stack_ly[i0 + top];
                clw    = stack_lw[i0 + top];
                cv     = cly - clw;
                cstart = ststart[i0 + top];
                --top;
            }
        }
        __syncthreads();

        // ---- block reduction of moments ----
        #pragma unroll
        for (int o = 16; o > 0; o >>= 1) {
            asum += __shfl_down_sync(0xFFFFFFFFu, asum, o);
            asq  += __shfl_down_sync(0xFFFFFFFFu, asq,  o);
            adot += __shfl_down_sync(0xFFFFFFFFu, adot, o);
        }
        int w = tid >> 5, l = tid & 31;
        if (l == 0) { scrA[w] = asum; scrB[w] = asq; redC[w] = adot; }
        __syncthreads();
        if (tid == 0) {
            float S = 0.0f, Q = 0.0f, D = 0.0f;
            #pragma unroll
            for (int w2 = 0; w2 < THREADS / 32; ++w2) {
                S += scrA[w2]; Q += scrB[w2]; D += redC[w2];
            }
            if (r == 0) {
                bcast[0] = S; bcast[1] = Q; bcast[2] = S / (float)N;
            } else {
                bcast[3] = S; bcast[4] = Q; bcast[5] = D;
            }
        }
        __syncthreads();
    }

    if (tid == 0) {
        float S1 = bcast[0], Q1 = bcast[1], m1 = bcast[2];
        float S2 = bcast[3], Q2 = bcast[4], D  = bcast[5];
        float m2  = S2 / (float)N;
        float num = D - m2 * (S1 - (float)N * m1);   // = sum(c1*c2) (exact correction)
        float v1  = Q1 - S1 * S1 / (float)N;
        float v2  = Q2 - S2 * S2 / (float)N;
        out[row] = 1.0f - num / (sqrtf(v1) * sqrtf(v2));
    }
}

extern "C" void kernel_launch(void* const* d_in, const int* in_sizes, int n_in,
                              void* d_out, int out_size)
{
    const float* x1 = (const float*)d_in[0];
    const float* x2 = (const float*)d_in[1];
    float* out = (float*)d_out;
    int rows = in_sizes[0] / N;   // 16*256 = 4096
    soft_spearman_kernel<<<rows, THREADS>>>(x1, x2, out);
}

// round 2
// speedup vs baseline: 1.6613x; 1.6613x over previous
#include <cuda_runtime.h>
#include <math.h>

#define N        2048
#define THREADS  256
#define EPN      8   // elements per thread

typedef unsigned long long u64;
typedef unsigned int       u32;
typedef unsigned short     u16;

__device__ __forceinline__ float logaddexpf_(float a, float b) {
    float mx = fmaxf(a, b);
    float mn = fminf(a, b);
    return mx + __logf(1.0f + __expf(mn - mx));
}

__global__ void __launch_bounds__(THREADS, 4)
soft_spearman_kernel(const float* __restrict__ x1,
                     const float* __restrict__ x2,
                     float* __restrict__ out)
{
    // Manually carved shared memory to allow phase-based aliasing:
    //  [0      , 16384) keyA   : radix ping buf / later prefmin+sufmax / later PAV stacks
    //  [16384  , 32768) region : radix pong buf / later v0s(8K)+perm(4K)+ststart(4K)
    //  [32768  , 40960) rank1  : row-1 ranks in original order (live across r)
    __shared__ __align__(16) unsigned char sraw[40960];
    __shared__ u16   whist[1024];       // [round(8)][warp(8)][digit(16)] counts
    __shared__ int   dbase[16];
    __shared__ float scrA[THREADS];
    __shared__ float scrB[THREADS];
    __shared__ float redC[8];
    __shared__ float bcast[8];

    u64*   keyA    = (u64*)sraw;
    u64*   keyB    = (u64*)(sraw + 16384);
    float* v0s     = (float*)(sraw + 16384);
    u16*   perm    = (u16*)(sraw + 16384 + 8192);
    u16*   ststart = (u16*)(sraw + 16384 + 12288);
    float* rank1   = (float*)(sraw + 32768);

    float* stack_ly = (float*)keyA;        // [0..N)
    float* stack_lw = ((float*)keyA) + N;  // [N..2N)
    float* prefm    = stack_ly;            // alias (scans precede stack usage)
    float* sufm     = stack_lw;

    const int row  = blockIdx.x;
    const int tid  = threadIdx.x;
    const int warp = tid >> 5;
    const int lane = tid & 31;
    const u32 lmask_lt = (1u << lane) - 1u;

    for (int r = 0; r < 2; ++r) {
        const float* x = (r == 0 ? x1 : x2) + (size_t)row * N;

        // ---- build sort keys: ascending key == descending theta, stable ties ----
        #pragma unroll
        for (int e = 0; e < EPN; ++e) {
            int i = e * THREADS + tid;
            float f = x[i] / 0.1f;                        // theta = x / EPS
            u32 u = __float_as_uint(f);
            u = (u & 0x80000000u) ? ~u : (u | 0x80000000u);  // order-preserving map
            keyA[i] = (((u64)(~u)) << 32) | (u32)i;
        }
        __syncthreads();

        // ---- stable LSD radix sort: 8 passes x 4 bits over key bits [32,64) ----
        u64* src = keyA;
        u64* dst = keyB;
        #pragma unroll 1
        for (int pass = 0; pass < 8; ++pass) {
            const int shift = 32 + pass * 4;

            // zero histogram (2KB / 256 threads = one u64 each)
            ((u64*)whist)[tid] = 0ULL;
            __syncthreads();

            // gather (conflict-free strided LDS.64) + warp-stable ranking
            u64 items[EPN];
            u32 lrp0 = 0, lrp1 = 0;   // packed per-item lane-ranks (8 bits each)
            #pragma unroll
            for (int e = 0; e < EPN; ++e) {
                u64 k = src[e * THREADS + tid];
                items[e] = k;
                int d = (int)(k >> shift) & 15;
                u32 m = __match_any_sync(0xFFFFFFFFu, d);
                int lr = __popc(m & lmask_lt);
                if (e < 4) lrp0 |= (u32)lr << (e * 8);
                else       lrp1 |= (u32)lr << ((e - 4) * 8);
                if ((m & lmask_lt) == 0)  // group leader (lowest lane)
                    whist[(e * 8 + warp) * 16 + d] = (u16)__popc(m);
            }
            __syncthreads();

            // per-digit exclusive scan over 64 (round-major, warp-minor) slots,
            // then digit-base exclusive scan (lanes 0..15 of warp 0)
            if (tid < 16) {
                int run = 0;
                #pragma unroll
                for (int j = 0; j < 64; ++j) {
                    int v = whist[j * 16 + tid];
                    whist[j * 16 + tid] = (u16)run;
                    run += v;
                }
                int tot = run;
                int inc = tot;
                #pragma unroll
                for (int o = 1; o < 16; o <<= 1) {
                    int v = __shfl_up_sync(0x0000FFFFu, inc, o, 16);
                    if (tid >= o) inc += v;
                }
                dbase[tid] = inc - tot;
            }
            __syncthreads();

            // scatter
            #pragma unroll
            for (int e = 0; e < EPN; ++e) {
                u64 k = items[e];
                int d  = (int)(k >> shift) & 15;
                int lr = (int)((e < 4 ? (lrp0 >> (e * 8)) : (lrp1 >> ((e - 4) * 8))) & 255u);
                int pos = dbase[d] + (int)whist[(e * 8 + warp) * 16 + d] + lr;
                dst[pos] = k;
            }
            __syncthreads();

            u64* t = src; src = dst; dst = t;   // 8 passes -> ends in keyA
        }

        // ---- extract v0 = s - log(n-i) and permutation (strided, conflict-free) ----
        #pragma unroll
        for (int e = 0; e < EPN; ++e) {
            int i = e * THREADS + tid;
            u64 K = keyA[i];
            u32 idx  = (u32)K & 0x7FFu;
            u32 u    = ~((u32)(K >> 32));
            u32 bits = (u & 0x80000000u) ? (u ^ 0x80000000u) : ~u;
            float s  = __uint_as_float(bits);
            v0s[i]   = s - __logf((float)(N - i));
            perm[i]  = (u16)idx;
        }
        __syncthreads();

        // ---- prefix-min / suffix-max of v0 (chunk-local + block scan) ----
        {
            int base = tid * EPN;
            float cmin = v0s[base], cmax = cmin;
            #pragma unroll
            for (int e = 1; e < EPN; ++e) {
                float f = v0s[base + e];
                cmin = fminf(cmin, f);
                cmax = fmaxf(cmax, f);
            }
            scrA[tid] = cmin;
            scrB[tid] = cmax;
            __syncthreads();
            for (int d = 1; d < THREADS; d <<= 1) {
                float a_cur = scrA[tid];
                float b_cur = scrB[tid];
                float a_prv = (tid >= d) ? scrA[tid - d] : 3.0e38f;
                float b_nxt = (tid + d < THREADS) ? scrB[tid + d] : -3.0e38f;
                __syncthreads();
                scrA[tid] = fminf(a_cur, a_prv);
                scrB[tid] = fmaxf(b_cur, b_nxt);
                __syncthreads();
            }
            float run = (tid > 0) ? scrA[tid - 1] : 3.0e38f;
            #pragma unroll
            for (int e = 0; e < EPN; ++e) {
                run = fminf(run, v0s[base + e]);
                prefm[base + e] = run;
            }
            float runx = (tid < THREADS - 1) ? scrB[tid + 1] : -3.0e38f;
            #pragma unroll
            for (int e = EPN - 1; e >= 0; --e) {
                runx = fmaxf(runx, v0s[base + e]);
                sufm[base + e] = runx;
            }
            __syncthreads();

            // guaranteed-boundary flags: prefmin[i] > sufmax[i+1]
            #pragma unroll
            for (int e = 0; e < EPN; ++e) {
                int i = base + e;
                if (i < N - 1 && prefm[i] > sufm[i + 1])
                    perm[i] |= 0x8000;
            }
            __syncthreads();
        }

        // ---- segmented PAV + fused emit (stacks alias keyA region) ----
        float asum = 0.0f, asq = 0.0f, adot = 0.0f;
        float m1v = (r == 1) ? bcast[2] : 0.0f;

        for (int i0 = tid; i0 < N; i0 += THREADS) {
            bool isStart = (i0 == 0) || (perm[i0 - 1] & 0x8000);
            if (!isStart) continue;

            float cv     = v0s[i0];
            float clw    = __logf((float)(N - i0));
            float cly    = cv + clw;
            int   cstart = i0;
            int   top    = -1;
            int   i      = i0;

            while (i + 1 < N && !(perm[i] & 0x8000)) {
                ++i;
                float v   = v0s[i];
                float lwi = __logf((float)(N - i));
                if (cv > v) {
                    // strictly decreasing: push current block, start new
                    ++top;
                    stack_ly[i0 + top] = cly;
                    stack_lw[i0 + top] = clw;
                    ststart [i0 + top] = (u16)cstart;
                    cly = v + lwi; clw = lwi; cv = v; cstart = i;
                } else {
                    // merge element i into current block, cascade left
                    cly = logaddexpf_(cly, v + lwi);
                    clw = logaddexpf_(clw, lwi);
                    cv  = cly - clw;
                    while (top >= 0) {
                        float ply = stack_ly[i0 + top];
                        float plw = stack_lw[i0 + top];
                        if (ply - plw > cv) break;
                        cly = logaddexpf_(ply, cly);
                        clw = logaddexpf_(plw, clw);
                        cv  = cly - clw;
                        cstart = ststart[i0 + top];
                        --top;
                    }
                }
            }

            // emit blocks back-to-front; fuse rank computation + scatter + moments
            int eend = i;
            for (;;) {
                for (int j = cstart; j <= eend; ++j) {
                    float rk = (float)(N - j) * __expf(v0s[j] - cv);
                    int   p  = perm[j] & 0x7FF;
                    if (r == 0) {
                        rank1[p] = rk;
                        asum += rk; asq += rk * rk;
                    } else {
                        asum += rk; asq += rk * rk;
                        adot += rk * (rank1[p] - m1v);
                    }
                }
                if (top < 0) break;
                eend   = cstart - 1;
                cly    = stack_ly[i0 + top];
                clw    = stack_lw[i0 + top];
                cv     = cly - clw;
                cstart = ststart[i0 + top];
                --top;
            }
        }
        __syncthreads();

        // ---- block reduction of moments ----
        #pragma unroll
        for (int o = 16; o > 0; o >>= 1) {
            asum += __shfl_down_sync(0xFFFFFFFFu, asum, o);
            asq  += __shfl_down_sync(0xFFFFFFFFu, asq,  o);
            adot += __shfl_down_sync(0xFFFFFFFFu, adot, o);
        }
        if (lane == 0) { scrA[warp] = asum; scrB[warp] = asq; redC[warp] = adot; }
        __syncthreads();
        if (tid == 0) {
            float S = 0.0f, Q = 0.0f, D = 0.0f;
            #pragma unroll
            for (int w2 = 0; w2 < THREADS / 32; ++w2) {
                S += scrA[w2]; Q += scrB[w2]; D += redC[w2];
            }
            if (r == 0) {
                bcast[0] = S; bcast[1] = Q; bcast[2] = S / (float)N;
            } else {
                bcast[3] = S; bcast[4] = Q; bcast[5] = D;
            }
        }
        __syncthreads();
    }

    if (tid == 0) {
        float S1 = bcast[0], Q1 = bcast[1], m1 = bcast[2];
        float S2 = bcast[3], Q2 = bcast[4], D  = bcast[5];
        float m2  = S2 / (float)N;
        float num = D - m2 * (S1 - (float)N * m1);   // = sum(c1*c2) (exact correction)
        float v1  = Q1 - S1 * S1 / (float)N;
        float v2  = Q2 - S2 * S2 / (float)N;
        out[row] = 1.0f - num / (sqrtf(v1) * sqrtf(v2));
    }
}

extern "C" void kernel_launch(void* const* d_in, const int* in_sizes, int n_in,
                              void* d_out, int out_size)
{
    const float* x1 = (const float*)d_in[0];
    const float* x2 = (const float*)d_in[1];
    float* out = (float*)d_out;
    int rows = in_sizes[0] / N;   // 16*256 = 4096
    soft_spearman_kernel<<<rows, THREADS>>>(x1, x2, out);
}

// round 3
// speedup vs baseline: 2.1635x; 1.3023x over previous
#include <cuda_runtime.h>
#include <math.h>

#define N        2048
#define THREADS  256
#define EPN      8   // elements per thread

typedef unsigned long long u64;
typedef unsigned int       u32;
typedef unsigned short     u16;

__device__ __forceinline__ float logaddexpf_(float a, float b) {
    float mx = fmaxf(a, b);
    float mn = fminf(a, b);
    return mx + __logf(1.0f + __expf(mn - mx));
}

// One stable 4-bit radix pass: items (gathered, order = e*THREADS+tid) -> dst.
// Caller must __syncthreads() between previous scatter and the gather of items.
__device__ __forceinline__ void radix_pass(
    u64* __restrict__ dst, const u64 items[EPN], int shift,
    u16* __restrict__ whist, int* __restrict__ dtot, int* __restrict__ dbase,
    int tid, int warp, int lane, u32 lmask_lt)
{
    // zero histogram (1088 u16 = 272 u64)
    ((u64*)whist)[tid] = 0ULL;
    if (tid < 16) ((u64*)whist)[256 + tid] = 0ULL;
    __syncthreads();

    // warp-stable ranking + per-(e,warp,digit) counts
    u32 lrp0 = 0, lrp1 = 0;
    #pragma unroll
    for (int e = 0; e < EPN; ++e) {
        int d = (int)(items[e] >> shift) & 15;
        u32 m = __match_any_sync(0xFFFFFFFFu, d);
        int lr = __popc(m & lmask_lt);
        if (e < 4) lrp0 |= (u32)lr << (e * 8);
        else       lrp1 |= (u32)lr << ((e - 4) * 8);
        if ((m & lmask_lt) == 0)  // group leader
            whist[(e * 8 + warp) * 17 + d] = (u16)__popc(m);
    }
    __syncthreads();

    // per-digit exclusive scan over the 64 slots: half-warp per digit
    {
        int h   = lane >> 4;
        int l16 = lane & 15;
        int d0  = 2 * warp + h;
        u32 v0 = whist[(4 * l16 + 0) * 17 + d0];
        u32 v1 = whist[(4 * l16 + 1) * 17 + d0];
        u32 v2 = whist[(4 * l16 + 2) * 17 + d0];
        u32 v3 = whist[(4 * l16 + 3) * 17 + d0];
        u32 tsum = v0 + v1 + v2 + v3;
        u32 incl = tsum;
        #pragma unroll
        for (int o = 1; o < 16; o <<= 1) {
            u32 t = __shfl_up_sync(0xFFFFFFFFu, incl, o, 16);
            if (l16 >= o) incl += t;
        }
        u32 excl = incl - tsum;
        whist[(4 * l16 + 0) * 17 + d0] = (u16)excl;
        whist[(4 * l16 + 1) * 17 + d0] = (u16)(excl + v0);
        whist[(4 * l16 + 2) * 17 + d0] = (u16)(excl + v0 + v1);
        whist[(4 * l16 + 3) * 17 + d0] = (u16)(excl + v0 + v1 + v2);
        if (l16 == 15) dtot[d0] = (int)incl;
    }
    __syncthreads();

    // digit-base exclusive scan (16 lanes)
    if (tid < 16) {
        int v = dtot[tid];
        int incl = v;
        #pragma unroll
        for (int o = 1; o < 16; o <<= 1) {
            int t = __shfl_up_sync(0x0000FFFFu, incl, o, 16);
            if (tid >= o) incl += t;
        }
        dbase[tid] = incl - v;
    }
    __syncthreads();

    // scatter
    #pragma unroll
    for (int e = 0; e < EPN; ++e) {
        u64 k = items[e];
        int d  = (int)(k >> shift) & 15;
        int lr = (int)((e < 4 ? (lrp0 >> (e * 8)) : (lrp1 >> ((e - 4) * 8))) & 255u);
        int pos = dbase[d] + (int)whist[(e * 8 + warp) * 17 + d] + lr;
        dst[pos] = k;
    }
    // caller syncs before reading dst
}

__global__ void __launch_bounds__(THREADS, 4)
soft_spearman_kernel(const float* __restrict__ x1,
                     const float* __restrict__ x2,
                     float* __restrict__ out)
{
    // [0      , 16384) keyA : radix ping / later prefmin+sufmax / later PAV stacks
    // [16384  , 32768) keyB : radix pong / later v0s(8K)+perm(4K)+ststart(4K)
    // [32768  , 40960) rank1: row-1 ranks in original order (live across r)
    __shared__ __align__(16) unsigned char sraw[40960];
    __shared__ __align__(8) u16 whist[1088];   // [slot(64)][digit(16)] padded *17
    __shared__ int   dtot[16];
    __shared__ int   dbase[16];
    __shared__ float scrA[THREADS];
    __shared__ float scrB[THREADS];
    __shared__ float redC[8];
    __shared__ float bcast[8];

    u64*   keyA    = (u64*)sraw;
    u64*   keyB    = (u64*)(sraw + 16384);
    float* v0s     = (float*)(sraw + 16384);
    u16*   perm    = (u16*)(sraw + 16384 + 8192);
    u16*   ststart = (u16*)(sraw + 16384 + 12288);
    float* rank1   = (float*)(sraw + 32768);

    float* stack_ly = (float*)keyA;        // [0..N)
    float* stack_lw = ((float*)keyA) + N;  // [N..2N)
    float* prefm    = stack_ly;            // alias (scans precede stack usage)
    float* sufm     = stack_lw;

    const int row  = blockIdx.x;
    const int tid  = threadIdx.x;
    const int warp = tid >> 5;
    const int lane = tid & 31;
    const u32 lmask_lt = (1u << lane) - 1u;

    for (int r = 0; r < 2; ++r) {
        const float* x = (r == 0 ? x1 : x2) + (size_t)row * N;

        // ---- pass 0: build keys directly from global (fused) ----
        u64 items[EPN];
        #pragma unroll
        for (int e = 0; e < EPN; ++e) {
            int i = e * THREADS + tid;
            float f = x[i] * 10.0f;                      // theta = x / EPS
            u32 u = __float_as_uint(f);
            u = (u & 0x80000000u) ? ~u : (u | 0x80000000u);  // order-preserving map
            items[e] = (((u64)(~u)) << 32) | (u32)i;
        }
        // pass 0 sorts bits [40,44); previous-phase smem use is guarded by the
        // sync at the end of the previous r-iteration / before first use.
        __syncthreads();
        radix_pass(keyB, items, 40, whist, dtot, dbase, tid, warp, lane, lmask_lt);

        // ---- passes 1..5 over bits [44,64) ----
        u64* src = keyB;
        u64* dst = keyA;
        #pragma unroll 1
        for (int pass = 1; pass < 6; ++pass) {
            __syncthreads();
            #pragma unroll
            for (int e = 0; e < EPN; ++e)
                items[e] = src[e * THREADS + tid];
            radix_pass(dst, items, 40 + 4 * pass, whist, dtot, dbase,
                       tid, warp, lane, lmask_lt);
            u64* t = src; src = dst; dst = t;   // ends with sorted data in keyA
        }
        __syncthreads();

        // ---- extract v0 = s - log(n-i) and permutation ----
        #pragma unroll
        for (int e = 0; e < EPN; ++e) {
            int i = e * THREADS + tid;
            u64 K = keyA[i];
            u32 idx  = (u32)K & 0x7FFu;
            u32 u    = ~((u32)(K >> 32));
            u32 bits = (u & 0x80000000u) ? (u ^ 0x80000000u) : ~u;
            float s  = __uint_as_float(bits);
            v0s[i]   = s - __logf((float)(N - i));
            perm[i]  = (u16)idx;
        }
        __syncthreads();

        // ---- prefix-min / suffix-max of v0 (chunk-local + block scan) ----
        {
            int base = tid * EPN;
            float cmin = v0s[base], cmax = cmin;
            #pragma unroll
            for (int e = 1; e < EPN; ++e) {
                float f = v0s[base + e];
                cmin = fminf(cmin, f);
                cmax = fmaxf(cmax, f);
            }
            scrA[tid] = cmin;
            scrB[tid] = cmax;
            __syncthreads();
            for (int d = 1; d < THREADS; d <<= 1) {
                float a_cur = scrA[tid];
                float b_cur = scrB[tid];
                float a_prv = (tid >= d) ? scrA[tid - d] : 3.0e38f;
                float b_nxt = (tid + d < THREADS) ? scrB[tid + d] : -3.0e38f;
                __syncthreads();
                scrA[tid] = fminf(a_cur, a_prv);
                scrB[tid] = fmaxf(b_cur, b_nxt);
                __syncthreads();
            }
            float run = (tid > 0) ? scrA[tid - 1] : 3.0e38f;
            #pragma unroll
            for (int e = 0; e < EPN; ++e) {
                run = fminf(run, v0s[base + e]);
                prefm[base + e] = run;
            }
            float runx = (tid < THREADS - 1) ? scrB[tid + 1] : -3.0e38f;
            #pragma unroll
            for (int e = EPN - 1; e >= 0; --e) {
                runx = fmaxf(runx, v0s[base + e]);
                sufm[base + e] = runx;
            }
            __syncthreads();

            // guaranteed-boundary flags: prefmin[i] > sufmax[i+1]
            #pragma unroll
            for (int e = 0; e < EPN; ++e) {
                int i = base + e;
                if (i < N - 1 && prefm[i] > sufm[i + 1])
                    perm[i] |= 0x8000;
            }
            __syncthreads();
        }

        // ---- segmented PAV + fused emit (stacks alias keyA region) ----
        float asum = 0.0f, asq = 0.0f, adot = 0.0f;
        float m1v = (r == 1) ? bcast[2] : 0.0f;

        for (int i0 = tid; i0 < N; i0 += THREADS) {
            bool isStart = (i0 == 0) || (perm[i0 - 1] & 0x8000);
            if (!isStart) continue;

            float cv     = v0s[i0];
            float clw    = __logf((float)(N - i0));
            float cly    = cv + clw;
            int   cstart = i0;
            int   top    = -1;
            int   i      = i0;

            while (i + 1 < N && !(perm[i] & 0x8000)) {
                ++i;
                float v   = v0s[i];
                float lwi = __logf((float)(N - i));
                if (cv > v) {
                    ++top;
                    stack_ly[i0 + top] = cly;
                    stack_lw[i0 + top] = clw;
                    ststart [i0 + top] = (u16)cstart;
                    cly = v + lwi; clw = lwi; cv = v; cstart = i;
                } else {
                    cly = logaddexpf_(cly, v + lwi);
                    clw = logaddexpf_(clw, lwi);
                    cv  = cly - clw;
                    while (top >= 0) {
                        float ply = stack_ly[i0 + top];
                        float plw = stack_lw[i0 + top];
                        if (ply - plw > cv) break;
                        cly = logaddexpf_(ply, cly);
                        clw = logaddexpf_(plw, clw);
                        cv  = cly - clw;
                        cstart = ststart[i0 + top];
                        --top;
                    }
                }
            }

            // emit blocks back-to-front; fuse rank computation + scatter + moments
            int eend = i;
            for (;;) {
                for (int j = cstart; j <= eend; ++j) {
                    float rk = (float)(N - j) * __expf(v0s[j] - cv);
                    int   p  = perm[j] & 0x7FF;
                    if (r == 0) {
                        rank1[p] = rk;
                        asum += rk; asq += rk * rk;
                    } else {
                        asum += rk; asq += rk * rk;
                        adot += rk * (rank1[p] - m1v);
                    }
                }
                if (top < 0) break;
                eend   = cstart - 1;
                cly    = stack_ly[i0 + top];
                clw    = stack_lw[i0 + top];
                cv     = cly - clw;
                cstart = ststart[i0 + top];
                --top;
            }
        }
        __syncthreads();

        // ---- block reduction of moments ----
        #pragma unroll
        for (int o = 16; o > 0; o >>= 1) {
            asum += __shfl_down_sync(0xFFFFFFFFu, asum, o);
            asq  += __shfl_down_sync(0xFFFFFFFFu, asq,  o);
            adot += __shfl_down_sync(0xFFFFFFFFu, adot, o);
        }
        if (lane == 0) { scrA[warp] = asum; scrB[warp] = asq; redC[warp] = adot; }
        __syncthreads();
        if (tid == 0) {
            float S = 0.0f, Q = 0.0f, D = 0.0f;
            #pragma unroll
            for (int w2 = 0; w2 < THREADS / 32; ++w2) {
                S += scrA[w2]; Q += scrB[w2]; D += redC[w2];
            }
            if (r == 0) {
                bcast[0] = S; bcast[1] = Q; bcast[2] = S / (float)N;
            } else {
                bcast[3] = S; bcast[4] = Q; bcast[5] = D;
            }
        }
        __syncthreads();
    }

    if (tid == 0) {
        float S1 = bcast[0], Q1 = bcast[1], m1 = bcast[2];
        float S2 = bcast[3], Q2 = bcast[4], D  = bcast[5];
        float m2  = S2 / (float)N;
        float num = D - m2 * (S1 - (float)N * m1);   // = sum(c1*c2) (exact correction)
        float v1  = Q1 - S1 * S1 / (float)N;
        float v2  = Q2 - S2 * S2 / (float)N;
        out[row] = 1.0f - num / (sqrtf(v1) * sqrtf(v2));
    }
}

extern "C" void kernel_launch(void* const* d_in, const int* in_sizes, int n_in,
                              void* d_out, int out_size)
{
    const float* x1 = (const float*)d_in[0];
    const float* x2 = (const float*)d_in[1];
    float* out = (float*)d_out;
    int rows = in_sizes[0] / N;   // 16*256 = 4096
    soft_spearman_kernel<<<rows, THREADS>>>(x1, x2, out);
}

// round 5
// speedup vs baseline: 2.3232x; 1.0738x over previous
#include <cuda_runtime.h>
#include <math.h>

#define N        2048
#define THREADS  256
#define EPN      8
#define FULLM    0xFFFFFFFFu

typedef unsigned long long u64;
typedef unsigned int       u32;
typedef unsigned short     u16;

__device__ __forceinline__ float logaddexpf_(float a, float b) {
    float mx = fmaxf(a, b);
    float mn = fminf(a, b);
    return mx + __logf(1.0f + __expf(mn - mx));
}

// One stable 7-bit radix pass, in-place. Caller has already gathered all keys
// into `items` (order = e*THREADS + tid). If LAST, scatter emits v0s/perm.
template <bool LAST>
__device__ __forceinline__ void radix_pass7(
    const u64 items[EPN], int shift,
    u16* __restrict__ whist, int* __restrict__ dbase,
    u64* __restrict__ keyA, float* __restrict__ v0s, u16* __restrict__ perm,
    int tid, int warp, int lane, u32 lt)
{
    // zero histogram: 16384B = 1024 uint4, 4 per thread (doesn't alias keyA)
    uint4 z = make_uint4(0, 0, 0, 0);
    #pragma unroll
    for (int q = 0; q < 4; ++q) ((uint4*)whist)[q * THREADS + tid] = z;
    __syncthreads();   // zeros visible AND all gathers complete (in-place safety)

    // warp-stable ranking + per-(e,warp,digit) counts
    u32 lr0 = 0, lr1 = 0;
    #pragma unroll
    for (int e = 0; e < EPN; ++e) {
        int d = (int)(items[e] >> shift) & 127;
        u32 m = __match_any_sync(FULLM, d);
        int lr = __popc(m & lt);
        if (e < 4) lr0 |= (u32)lr << (e * 8);
        else       lr1 |= (u32)lr << ((e - 4) * 8);
        if ((m & lt) == 0)   // group leader (lowest lane with this digit)
            whist[(e * 8 + warp) * 128 + d] = (u16)__popc(m);
    }
    __syncthreads();

    // warp 0: per-digit exclusive scan over 64 slots (lane owns 4 digit cols),
    // then 128-digit base scan via 4 warp scans.
    if (warp == 0) {
        u32 run0 = 0, run1 = 0, run2 = 0, run3 = 0;
        #pragma unroll 4
        for (int s = 0; s < 64; ++s) {
            u16* rowp = whist + s * 128;
            u32 v;
            v = rowp[lane     ]; rowp[lane     ] = (u16)run0; run0 += v;
            v = rowp[lane + 32]; rowp[lane + 32] = (u16)run1; run1 += v;
            v = rowp[lane + 64]; rowp[lane + 64] = (u16)run2; run2 += v;
            v = rowp[lane + 96]; rowp[lane + 96] = (u16)run3; run3 += v;
        }
        u32 a = run0, ai = a;
        #pragma unroll
        for (int o = 1; o < 32; o <<= 1) { u32 t = __shfl_up_sync(FULLM, ai, o); if (lane >= o) ai += t; }
        u32 tA = __shfl_sync(FULLM, ai, 31);
        u32 b = run1, bi = b;
        #pragma unroll
        for (int o = 1; o < 32; o <<= 1) { u32 t = __shfl_up_sync(FULLM, bi, o); if (lane >= o) bi += t; }
        u32 tB = __shfl_sync(FULLM, bi, 31);
        u32 c = run2, ci = c;
        #pragma unroll
        for (int o = 1; o < 32; o <<= 1) { u32 t = __shfl_up_sync(FULLM, ci, o); if (lane >= o) ci += t; }
        u32 tC = __shfl_sync(FULLM, ci, 31);
        u32 d4 = run3, di = d4;
        #pragma unroll
        for (int o = 1; o < 32; o <<= 1) { u32 t = __shfl_up_sync(FULLM, di, o); if (lane >= o) di += t; }
        dbase[lane     ] = (int)(ai - a);
        dbase[lane + 32] = (int)(tA + bi - b);
        dbase[lane + 64] = (int)(tA + tB + ci - c);
        dbase[lane + 96] = (int)(tA + tB + tC + di - d4);
    }
    __syncthreads();

    // scatter (in-place into keyA, or v0s/perm for the last pass)
    #pragma unroll
    for (int e = 0; e < EPN; ++e) {
        u64 k = items[e];
        int d  = (int)(k >> shift) & 127;
        int lr = (int)((e < 4 ? (lr0 >> (e * 8)) : (lr1 >> ((e - 4) * 8))) & 255u);
        int pos = dbase[d] + (int)whist[(e * 8 + warp) * 128 + d] + lr;
        if (LAST) {
            u32 idx  = (u32)k & 0x7FFu;
            u32 u    = ~((u32)(k >> 32));
            u32 bits = (u & 0x80000000u) ? (u ^ 0x80000000u) : ~u;
            v0s[pos]  = __uint_as_float(bits) - __logf((float)(N - pos));
            perm[pos] = (u16)idx;
        } else {
            keyA[pos] = k;
        }
    }
    __syncthreads();
}

__global__ void __launch_bounds__(THREADS, 4)
soft_spearman_kernel(const float* __restrict__ x1,
                     const float* __restrict__ x2,
                     float* __restrict__ out)
{
    // Static smem, 40.6KB total:
    //  [0    , 16384) keyA (in-place radix) -> v0s[0,8K) + perm[8K,12K) + ststart[12K,16K)
    //  [16384, 32768) whist u16[64][128] (radix)  /  PAV stacks ly+lw (8K each)
    //  [32768, 40960) rank1 (row-1 ranks, original order; live across r)
    __shared__ __align__(16) unsigned char sraw[40960];
    __shared__ int   dbase[128];
    __shared__ float scrA[8];
    __shared__ float scrB[8];
    __shared__ float scrC[8];
    __shared__ float bcast[8];

    u64*   keyA     = (u64*)sraw;
    float* v0s      = (float*)sraw;
    u16*   perm     = (u16*)(sraw + 8192);
    u16*   ststart  = (u16*)(sraw + 12288);
    u16*   whist    = (u16*)(sraw + 16384);
    float* stack_ly = (float*)(sraw + 16384);
    float* stack_lw = (float*)(sraw + 24576);
    float* rank1    = (float*)(sraw + 32768);

    const int row  = blockIdx.x;
    const int tid  = threadIdx.x;
    const int warp = tid >> 5;
    const int lane = tid & 31;
    const u32 lt   = (1u << lane) - 1u;

    for (int r = 0; r < 2; ++r) {
        const float* x = (r == 0 ? x1 : x2) + (size_t)row * N;

        // ---- build keys from global; 3 stable passes x 7 bits over [43,64) ----
        u64 items[EPN];
        #pragma unroll
        for (int e = 0; e < EPN; ++e) {
            int i = e * THREADS + tid;
            float f = x[i] * 10.0f;                      // theta = x / EPS
            u32 u = __float_as_uint(f);
            u = (u & 0x80000000u) ? ~u : (u | 0x80000000u);  // order-preserving
            items[e] = (((u64)(~u)) << 32) | (u32)i;
        }
        radix_pass7<false>(items, 43, whist, dbase, keyA, v0s, perm, tid, warp, lane, lt);
        #pragma unroll
        for (int e = 0; e < EPN; ++e) items[e] = keyA[e * THREADS + tid];
        radix_pass7<false>(items, 50, whist, dbase, keyA, v0s, perm, tid, warp, lane, lt);
        #pragma unroll
        for (int e = 0; e < EPN; ++e) items[e] = keyA[e * THREADS + tid];
        radix_pass7<true >(items, 57, whist, dbase, keyA, v0s, perm, tid, warp, lane, lt);
        // v0s / perm complete (pass ends with a syncthreads)

        // ---- prefix-min / suffix-max boundary flags via shuffle scans ----
        {
            int base = tid * EPN;
            float c[8];
            float4 q0 = *(float4*)(v0s + base);
            float4 q1 = *(float4*)(v0s + base + 4);
            c[0]=q0.x; c[1]=q0.y; c[2]=q0.z; c[3]=q0.w;
            c[4]=q1.x; c[5]=q1.y; c[6]=q1.z; c[7]=q1.w;
            float cmin = c[0], cmax = c[0];
            #pragma unroll
            for (int e = 1; e < 8; ++e) { cmin = fminf(cmin, c[e]); cmax = fmaxf(cmax, c[e]); }

            float pm = cmin;   // inclusive prefix-min over threads (chunk granularity)
            #pragma unroll
            for (int o = 1; o < 32; o <<= 1) {
                float t = __shfl_up_sync(FULLM, pm, o);
                if (lane >= o) pm = fminf(pm, t);
            }
            float sm = cmax;   // inclusive suffix-max
            #pragma unroll
            for (int o = 1; o < 32; o <<= 1) {
                float t = __shfl_down_sync(FULLM, sm, o);
                if (lane < 32 - o) sm = fmaxf(sm, t);
            }
            if (lane == 31) scrA[warp] = pm;   // whole-warp min
            if (lane == 0)  scrB[warp] = sm;   // whole-warp max
            __syncthreads();
            float preW = 3.0e38f, sufW = -3.0e38f;
            #pragma unroll
            for (int j = 0; j < 8; ++j) {
                float wm = scrA[j], wx = scrB[j];
                if (j < warp) preW = fminf(preW, wm);
                if (j > warp) sufW = fmaxf(sufW, wx);
            }
            float pmPrev = __shfl_up_sync(FULLM, pm, 1);
            float pexcl  = (lane == 0)  ? preW : fminf(preW, pmPrev);
            float smNext = __shfl_down_sync(FULLM, sm, 1);
            float sexcl  = (lane == 31) ? sufW : fmaxf(sufW, smNext);

            float suf[8];
            float t = sexcl;
            #pragma unroll
            for (int e = 7; e >= 0; --e) { suf[e] = fmaxf(c[e], t); t = suf[e]; }
            float run = pexcl;
            #pragma unroll
            for (int e = 0; e < 8; ++e) {
                run = fminf(run, c[e]);                    // inclusive prefmin at base+e
                float nxt = (e < 7) ? suf[e + 1] : sexcl;  // inclusive sufmax at base+e+1
                if (run > nxt) perm[base + e] |= 0x8000;   // guaranteed boundary
            }
            __syncthreads();
        }

        // ---- segmented PAV + fused emit (stacks alias whist region) ----
        float asum = 0.0f, asq = 0.0f, adot = 0.0f;
        float m1v = (r == 1) ? bcast[2] : 0.0f;

        for (int i0 = tid; i0 < N; i0 += THREADS) {
            bool isStart = (i0 == 0) || (perm[i0 - 1] & 0x8000);
            if (!isStart) continue;

            // singleton fast path: rank is exactly N - i0
            if ((perm[i0] & 0x8000) || i0 == N - 1) {
                float rk = (float)(N - i0);
                int   p  = perm[i0] & 0x7FF;
                if (r == 0) { rank1[p] = rk; asum += rk; asq += rk * rk; }
                else        { asum += rk; asq += rk * rk; adot += rk * (rank1[p] - m1v); }
                continue;
            }

            float cv     = v0s[i0];
            float clw    = __logf((float)(N - i0));
            float cly    = cv + clw;
            int   cstart = i0;
            int   top    = -1;
            int   i      = i0;

            while (i + 1 < N && !(perm[i] & 0x8000)) {
                ++i;
                float v   = v0s[i];
                float lwi = __logf((float)(N - i));
                if (cv > v) {
                    ++top;
                    stack_ly[i0 + top] = cly;
                    stack_lw[i0 + top] = clw;
                    ststart [i0 + top] = (u16)cstart;
                    cly = v + lwi; clw = lwi; cv = v; cstart = i;
                } else {
                    cly = logaddexpf_(cly, v + lwi);
                    clw = logaddexpf_(clw, lwi);
                    cv  = cly - clw;
                    while (top >= 0) {
                        float ply = stack_ly[i0 + top];
                        float plw = stack_lw[i0 + top];
                        if (ply - plw > cv) break;
                        cly = logaddexpf_(ply, cly);
                        clw = logaddexpf_(plw, clw);
                        cv  = cly - clw;
                        cstart = ststart[i0 + top];
                        --top;
                    }
                }
            }

            // emit blocks back-to-front
            int eend = i;
            for (;;) {
                for (int j = cstart; j <= eend; ++j) {
                    float rk = (float)(N - j) * __expf(v0s[j] - cv);
                    int   p  = perm[j] & 0x7FF;
                    if (r == 0) { rank1[p] = rk; asum += rk; asq += rk * rk; }
                    else        { asum += rk; asq += rk * rk; adot += rk * (rank1[p] - m1v); }
                }
                if (top < 0) break;
                eend   = cstart - 1;
                cly    = stack_ly[i0 + top];
                clw    = stack_lw[i0 + top];
                cv     = cly - clw;
                cstart = ststart[i0 + top];
                --top;
            }
        }
        __syncthreads();

        // ---- block reduction of moments ----
        #pragma unroll
        for (int o = 16; o > 0; o >>= 1) {
            asum += __shfl_down_sync(FULLM, asum, o);
            asq  += __shfl_down_sync(FULLM, asq,  o);
            adot += __shfl_down_sync(FULLM, adot, o);
        }
        if (lane == 0) { scrA[warp] = asum; scrB[warp] = asq; scrC[warp] = adot; }
        __syncthreads();
        if (tid == 0) {
            float S = 0.0f, Q = 0.0f, D = 0.0f;
            #pragma unroll
            for (int w2 = 0; w2 < 8; ++w2) { S += scrA[w2]; Q += scrB[w2]; D += scrC[w2]; }
            if (r == 0) { bcast[0] = S; bcast[1] = Q; bcast[2] = S / (float)N; }
            else        { bcast[3] = S; bcast[4] = Q; bcast[5] = D; }
        }
        __syncthreads();
    }

    if (tid == 0) {
        float S1 = bcast[0], Q1 = bcast[1], m1 = bcast[2];
        float S2 = bcast[3], Q2 = bcast[4], D  = bcast[5];
        float m2  = S2 / (float)N;
        float num = D - m2 * (S1 - (float)N * m1);
        float v1  = Q1 - S1 * S1 / (float)N;
        float v2  = Q2 - S2 * S2 / (float)N;
        out[row] = 1.0f - num / (sqrtf(v1) * sqrtf(v2));
    }
}

extern "C" void kernel_launch(void* const* d_in, const int* in_sizes, int n_in,
                              void* d_out, int out_size)
{
    const float* x1 = (const float*)d_in[0];
    const float* x2 = (const float*)d_in[1];
    float* out = (float*)d_out;
    int rows = in_sizes[0] / N;   // 4096
    soft_spearman_kernel<<<rows, THREADS>>>(x1, x2, out);
}